// round 11
// baseline (speedup 1.0000x reference)
#include <cuda_runtime.h>

#define NBLK 128
#define TPB  288          // 9 warps: 8 MLP-row warps + 1 SEIR warp
#define WID  1024
#define HID  256
#define NST  17
#define NY   273          // 17 + 256
#define XPAD 288
#define RH   8            // hidden rows per block (1 per warp)
#define RL   2            // output rows per block (warps 0-1)
#define T_N  64
#define SUB  8
#define NHID 3

// ---------------- global scratch (no allocs allowed) ----------------
__device__ __align__(16) float g_z[2][WID];   // double-buffered layer activations
__device__ float g_k[2][4][NY];               // RK4 slopes, parity-buffered
__device__ unsigned g_cnt;                    // arrival counter (reset each launch)

// ---------------- shared memory layout (floats) ----------------
#define OFF_Z0   0
#define OFF_Z1   (OFF_Z0 + WID)
#define OFF_X    (OFF_Z1 + WID)
#define OFF_B0   (OFF_X + XPAD)
#define OFF_BH   (OFF_B0 + RH)
#define OFF_BL   (OFF_BH + NHID*RH)
#define OFF_BB   (OFF_BL + RL)
#define OFF_BW   (OFF_BB + 1)
#define SMEM_FLOATS (OFF_BW + HID)
#define SMEM_BYTES  (SMEM_FLOATS * 4)      // ~10.4 KB

__device__ __forceinline__ unsigned ld_acq(unsigned* p) {
    unsigned v;
    asm volatile("ld.acquire.gpu.global.u32 %0, [%1];" : "=r"(v) : "l"(p) : "memory");
    return v;
}
__device__ __forceinline__ void red_rel_add(unsigned* p, unsigned v) {
    asm volatile("red.release.gpu.global.add.u32 [%0], %1;" :: "l"(p), "r"(v) : "memory");
}

// Grid barrier (proven protocol): bar.sync + release-RED arrival +
// acquire-load poll. Every observation of the counter is an acquire.
// Poll is 2x-unrolled: the two independent acquire loads pipeline, halving
// the effective sampling interval; counter-line traffic stays under the LTS
// per-line service rate.
__device__ __forceinline__ void gridbar(unsigned tgt) {
    __syncthreads();
    if (threadIdx.x == 0) {
        red_rel_add(&g_cnt, 1u);
        for (;;) {
            unsigned v0 = ld_acq(&g_cnt);
            unsigned v1 = ld_acq(&g_cnt);
            if (((int)(v0 - tgt) >= 0) | ((int)(v1 - tgt) >= 0)) break;
        }
    }
    __syncthreads();
}

__device__ __forceinline__ float softplus_f(float v) {
    return fmaxf(v, 0.f) + log1pf(expf(-fabsf(v)));
}

__device__ __forceinline__ float warp_sum(float a) {
#pragma unroll
    for (int o = 16; o > 0; o >>= 1) a += __shfl_xor_sync(0xffffffffu, a, o);
    return a;
}

__global__ void reset_kernel() { g_cnt = 0u; }

__global__ void __launch_bounds__(TPB, 1)
ode_kernel(const float* __restrict__ ts,  const float* __restrict__ W0,
           const float* __restrict__ b0,  const float* __restrict__ Wh,
           const float* __restrict__ bh,  const float* __restrict__ Wl,
           const float* __restrict__ bl,  const float* __restrict__ bW,
           const float* __restrict__ bb,  const float* __restrict__ hvec,
           const float* __restrict__ scale, const float* __restrict__ y0log,
           float* __restrict__ out)
{
    extern __shared__ float sm[];
    const int tid  = threadIdx.x;
    const int b    = blockIdx.x;
    const int warp = tid >> 5;
    const int lane = tid & 31;

    float* sx  = sm + OFF_X;
    float* sb0 = sm + OFF_B0;
    float* sbh = sm + OFF_BH;
    float* sbl = sm + OFF_BL;
    float* sbw = sm + OFF_BW;

    unsigned tgt = 0;   // barrier target; g_cnt was zeroed by reset_kernel

    // ---- ALL weights in registers ----
    float w0r[9];
#pragma unroll
    for (int i = 0; i < 9; i++) {
        int col = lane + 32 * i;
        w0r[i] = (warp < 8 && col < 273)
                 ? __ldg(&W0[(b * RH + warp) * 273 + col]) : 0.f;
    }
    float4 wh[NHID][8];
#pragma unroll
    for (int l = 0; l < NHID; l++)
#pragma unroll
        for (int i = 0; i < 8; i++)
            wh[l][i] = (warp < 8)
                ? __ldg((const float4*)&Wh[((l * WID) + (b * RH + warp)) * WID
                                           + lane * 4 + 128 * i])
                : make_float4(0.f, 0.f, 0.f, 0.f);
    float4 wl[8];
#pragma unroll
    for (int i = 0; i < 8; i++)
        wl[i] = (warp < RL)
            ? __ldg((const float4*)&Wl[(b * RL + warp) * WID + lane * 4 + 128 * i])
            : make_float4(0.f, 0.f, 0.f, 0.f);

    // ---- small constants into smem ----
    if (tid < RH) sb0[tid] = b0[b * RH + tid];
    if (tid >= 32 && tid < 32 + NHID * RH) {
        int i = tid - 32; int l = i >> 3, r = i & 7;
        sbh[i] = bh[l * WID + b * RH + r];
    }
    if (tid >= 64 && tid < 64 + RL) sbl[tid - 64] = bl[b * RL + (tid - 64)];
    if (tid == 66) sm[OFF_BB] = bb[0];
    for (int idx = tid; idx < HID; idx += TPB) sbw[idx] = bW[idx];
    if (tid >= NY && tid < XPAD) sx[tid] = 0.f;   // zero-pad tail of x (stays 0)

    // ---- per-thread state registers (tid < NY): y, k1..k3 ----
    float y = 0.f, k1 = 0.f, k2 = 0.f, k3 = 0.f;
    if (tid < NY) {
        if (tid < NST) {
            float m = -1e30f;
            for (int i = 0; i < NST; i++) m = fmaxf(m, __ldg(&y0log[i]));
            float s = 0.f;
            for (int i = 0; i < NST; i++) s += expf(__ldg(&y0log[i]) - m);
            y = expf(__ldg(&y0log[tid]) - m) / s;
        } else {
            y = __ldg(&hvec[tid - NST]);
        }
    }
    __syncthreads();

    const float scl = scale[0];

    if (b == 0 && tid < NY) {                     // output row 0
        if (tid < NST) out[tid] = y;
        else           out[T_N * NST + (tid - NST)] = y;
    }

    for (int iv = 0; iv < T_N - 1; ++iv) {
        float dt  = (__ldg(&ts[iv + 1]) - __ldg(&ts[iv])) * (1.f / (float)SUB);
        float dt6 = dt * (1.f / 6.f);
        for (int ss = 0; ss < SUB; ++ss) {
            const int par = (iv * SUB + ss) & 1;
#pragma unroll
            for (int st = 0; st < 4; ++st) {
                // ---- x-build: read k[st-1] (visible since last barrier) ----
                if (tid < NY) {
                    float xv = y;
                    if (st > 0) {
                        float kp = __ldcg(&g_k[par][st - 1][tid]);
                        if (st == 1) k1 = kp; else if (st == 2) k2 = kp; else k3 = kp;
                        xv = fmaf((st == 3) ? dt : 0.5f * dt, kp, y);
                    }
                    sx[(tid < NST) ? (HID + tid) : (tid - NST)] = xv;
                }
                __syncthreads();

                if (warp < 8) {
                    // ---- layer 0: 273 -> 1024, 1 row per warp, reg weights ----
                    float acc = 0.f;
#pragma unroll
                    for (int i = 0; i < 9; i++)
                        acc = fmaf(w0r[i], sx[lane + 32 * i], acc);
                    acc = warp_sum(acc);
                    if (lane == 0)
                        __stcg(&g_z[0][b * RH + warp], softplus_f(acc + sb0[warp]));
                } else if (b == 0) {
                    // ---- dedicated SEIR warp (block 0, warp 8) ----
                    float t = 0.f;
#pragma unroll
                    for (int i = 0; i < 8; i++) {
                        int k = lane + 32 * i;
                        t = fmaf(sbw[k], sx[k], t);
                    }
                    t = warp_sum(t);
                    if (lane == 0) {
                        float bb1 = 8.f / (1.f + expf(-(t + sm[OFF_BB]))) + 25.f;
                        const float MU   = (float)(0.041 / 12.0);
                        const float XI   = (float)(13.0 / 12.0);
                        const float XIMU = (float)(13.0 / 12.0 + 0.041 / 12.0);
                        const float MUSG = (float)(0.041 / 12.0 + 91.0 / 12.0);
                        const float SG   = (float)(91.0 / 12.0);
                        const float NU   = (float)(36.0 / 12.0);
                        const float NUMU = (float)(36.0 / 12.0 + 0.041 / 12.0);
                        const float MUGA = (float)(0.041 / 12.0 + 1.8 / 12.0);
                        const float GA   = (float)(1.8 / 12.0);
                        const float* s_ = &sx[HID];
                        float M  = s_[0],  S1 = s_[1],  E1 = s_[2],  E2 = s_[3];
                        float E3 = s_[4],  E4 = s_[5],  I1 = s_[6],  I2 = s_[7];
                        float I3 = s_[8],  I4 = s_[9],  R1 = s_[10], R2 = s_[11];
                        float R3 = s_[12], R4 = s_[13], S2 = s_[14], S3 = s_[15];
                        float S4 = s_[16];
                        float I = I1 + I2 + I3 + I4;
                        float R = R1 + R2 + R3 + R4;
                        float bb2 = 0.5f * bb1, bb3 = 0.35f * bb1, bb4 = 0.25f * bb1;
                        float d[NST];
                        d[0]  = R * MU - XIMU * M;
                        d[1]  = MU * (1.f - R) + XI * M - MU * S1 - bb1 * I * S1;
                        d[2]  = bb1 * I * S1 - MUSG * E1;
                        d[3]  = bb2 * I * S2 - MUSG * E2;
                        d[4]  = bb3 * I * S3 - MUSG * E3;
                        d[5]  = bb4 * I * S4 - MUSG * E4;
                        d[6]  = SG * E1 - NUMU * I1;
                        d[7]  = SG * E2 - NUMU * I2;
                        d[8]  = SG * E3 - NUMU * I3;
                        d[9]  = SG * E4 - NUMU * I4;
                        d[10] = NU * I1 - MUGA * R1;
                        d[11] = NU * I2 - MUGA * R2;
                        d[12] = NU * I3 - MUGA * R3;
                        d[13] = NU * I4 - MUGA * R4;
                        d[14] = GA * R1 - MU * S2 - bb2 * I * S2;
                        d[15] = GA * R2 - MU * S3 - bb3 * I * S3;
                        d[16] = GA * (R3 + R4) - MU * S4 - bb4 * I * S4;
#pragma unroll
                        for (int i2 = 0; i2 < NST; i2++)
                            __stcg(&g_k[par][st][i2], d[i2]);
                    }
                }
                tgt += NBLK; gridbar(tgt);

                // ---- 3 hidden layers + final: z staged in ALTERNATING smem
                // buffers so the global fetch never waits on prior readers ----
#pragma unroll
                for (int l = 0; l < NHID; l++) {
                    float* szl = sm + ((l & 1) ? OFF_Z1 : OFF_Z0);
                    if (tid < 256)
                        *(float4*)&szl[tid * 4] =
                            __ldcg((const float4*)&g_z[l & 1][tid * 4]);
                    __syncthreads();
                    if (warp < 8) {
                        float acc = 0.f;
                        const float4* z4 = (const float4*)szl;
#pragma unroll
                        for (int i = 0; i < 8; i++) {
                            float4 z = z4[lane + 32 * i];
                            float4 a = wh[l][i];
                            acc = fmaf(a.x, z.x, acc);
                            acc = fmaf(a.y, z.y, acc);
                            acc = fmaf(a.z, z.z, acc);
                            acc = fmaf(a.w, z.w, acc);
                        }
                        acc = warp_sum(acc);
                        if (lane == 0)
                            __stcg(&g_z[(l & 1) ^ 1][b * RH + warp],
                                   softplus_f(acc + sbh[l * RH + warp]));
                    }
                    tgt += NBLK; gridbar(tgt);
                }

                // ---- final layer: 1024 -> 256, warps 0-1, reg weights ----
                {
                    float* szl = sm + OFF_Z1;   // layer 2 wrote g_z[1]; stage in Z1
                    if (tid < 256)
                        *(float4*)&szl[tid * 4] =
                            __ldcg((const float4*)&g_z[1][tid * 4]);
                    __syncthreads();
                    if (warp < RL) {
                        float acc = 0.f;
                        const float4* z4 = (const float4*)szl;
#pragma unroll
                        for (int i = 0; i < 8; i++) {
                            float4 z = z4[lane + 32 * i];
                            float4 a = wl[i];
                            acc = fmaf(a.x, z.x, acc);
                            acc = fmaf(a.y, z.y, acc);
                            acc = fmaf(a.z, z.z, acc);
                            acc = fmaf(a.w, z.w, acc);
                        }
                        acc = warp_sum(acc);
                        if (lane == 0) {
                            float u = tanhf(0.01f * (acc + sbl[warp]));
                            __stcg(&g_k[par][st][NST + b * RL + warp], scl * u);
                        }
                    }
                }
                tgt += NBLK; gridbar(tgt);
            } // st

            // ---- RK4 combine (registers; k4 visible since last barrier) ----
            if (tid < NY) {
                float k4 = __ldcg(&g_k[par][3][tid]);
                y = fmaf(dt6, k1 + 2.f * (k2 + k3) + k4, y);
            }
        } // ss

        if (b == 0 && tid < NY) {
            if (tid < NST) out[(iv + 1) * NST + tid] = y;
            else           out[T_N * NST + (iv + 1) * HID + (tid - NST)] = y;
        }
    } // iv
}

extern "C" void kernel_launch(void* const* d_in, const int* in_sizes, int n_in,
                              void* d_out, int out_size) {
    (void)in_sizes; (void)n_in; (void)out_size;
    const float* ts    = (const float*)d_in[0];
    const float* W0    = (const float*)d_in[1];
    const float* b0    = (const float*)d_in[2];
    const float* Wh    = (const float*)d_in[3];
    const float* bh    = (const float*)d_in[4];
    const float* Wl    = (const float*)d_in[5];
    const float* bl    = (const float*)d_in[6];
    const float* bW    = (const float*)d_in[7];
    const float* bb    = (const float*)d_in[8];
    const float* hvec  = (const float*)d_in[9];
    const float* scale = (const float*)d_in[10];
    const float* y0log = (const float*)d_in[11];
    float* out = (float*)d_out;

    cudaFuncSetAttribute(ode_kernel,
                         cudaFuncAttributeMaxDynamicSharedMemorySize, SMEM_BYTES);
    reset_kernel<<<1, 1>>>();
    ode_kernel<<<NBLK, TPB, SMEM_BYTES>>>(ts, W0, b0, Wh, bh, Wl, bl, bW, bb,
                                          hvec, scale, y0log, out);
}

// round 12
// speedup vs baseline: 1.1287x; 1.1287x over previous
#include <cuda_runtime.h>

#define TPB   288
#define NGRID 144          // g0:32  g1-g3:32 each  g4:16  (<=148 SMs, all resident)
#define WID   1024
#define HID   256
#define NST   17
#define NY    273
#define T_N   64
#define SUB   8
#define NSTAGE 2016        // 63 intervals * 8 substeps * 4 RK stages

// ---------------- global scratch (no allocs) ----------------
__device__ __align__(16) float g_zb[4][WID];   // z0..z3 (single-buffered, ring-safe)
__device__ __align__(16) float g_dh[HID];      // final-layer output (scaled)
__device__ unsigned g_lnk[5 * 32];             // 5 link counters, separate lines

__device__ __forceinline__ unsigned ld_acq(unsigned* p) {
    unsigned v;
    asm volatile("ld.acquire.gpu.global.u32 %0, [%1];" : "=r"(v) : "l"(p) : "memory");
    return v;
}
__device__ __forceinline__ void red_rel_add(unsigned* p, unsigned v) {
    asm volatile("red.release.gpu.global.add.u32 [%0], %1;" :: "l"(p), "r"(v) : "memory");
}

// link wait: acquire-poll by thread 0 (proven primitive), then CTA bar
__device__ __forceinline__ void wait_lnk(int l, unsigned tgt) {
    if (threadIdx.x == 0) {
        unsigned v;
        do { v = ld_acq(&g_lnk[l * 32]); } while ((int)(v - tgt) < 0);
    }
    __syncthreads();
}
// link publish: CTA bar (orders all warps' stcg), then release-RED by thread 0
__device__ __forceinline__ void pub_lnk(int l) {
    __syncthreads();
    if (threadIdx.x == 0) red_rel_add(&g_lnk[l * 32], 1u);
}

__device__ __forceinline__ float softplus_f(float v) {
    return fmaxf(v, 0.f) + log1pf(expf(-fabsf(v)));
}

// full 32-lane sum (5-shfl tree)
__device__ __forceinline__ float warp_sum(float a) {
#pragma unroll
    for (int o = 16; o > 0; o >>= 1) a += __shfl_xor_sync(0xffffffffu, a, o);
    return a;
}

// 4-row reduce: fold quads, select row by lane&3, fold across quads.
// Result: lane j (j<4) holds full sum of row j.
__device__ __forceinline__ float reduce4(float a0, float a1, float a2, float a3,
                                         int lane) {
    a0 += __shfl_xor_sync(0xffffffffu, a0, 1);
    a1 += __shfl_xor_sync(0xffffffffu, a1, 1);
    a2 += __shfl_xor_sync(0xffffffffu, a2, 1);
    a3 += __shfl_xor_sync(0xffffffffu, a3, 1);
    a0 += __shfl_xor_sync(0xffffffffu, a0, 2);
    a1 += __shfl_xor_sync(0xffffffffu, a1, 2);
    a2 += __shfl_xor_sync(0xffffffffu, a2, 2);
    a3 += __shfl_xor_sync(0xffffffffu, a3, 2);
    float v = (lane & 2) ? ((lane & 1) ? a3 : a2) : ((lane & 1) ? a1 : a0);
    v += __shfl_xor_sync(0xffffffffu, v, 4);
    v += __shfl_xor_sync(0xffffffffu, v, 8);
    v += __shfl_xor_sync(0xffffffffu, v, 16);
    return v;
}

// 2-row reduce: lane j (j<2) holds full sum of row j.
__device__ __forceinline__ float reduce2(float a0, float a1, int lane) {
    a0 += __shfl_xor_sync(0xffffffffu, a0, 1);
    a1 += __shfl_xor_sync(0xffffffffu, a1, 1);
    float v = (lane & 1) ? a1 : a0;
    v += __shfl_xor_sync(0xffffffffu, v, 2);
    v += __shfl_xor_sync(0xffffffffu, v, 4);
    v += __shfl_xor_sync(0xffffffffu, v, 8);
    v += __shfl_xor_sync(0xffffffffu, v, 16);
    return v;
}

__global__ void reset_kernel() {
    for (int i = 0; i < 5; i++) g_lnk[i * 32] = 0u;
}

__global__ void __launch_bounds__(TPB, 1)
ode_kernel(const float* __restrict__ ts,  const float* __restrict__ W0,
           const float* __restrict__ b0,  const float* __restrict__ Wh,
           const float* __restrict__ bh,  const float* __restrict__ Wl,
           const float* __restrict__ bl,  const float* __restrict__ bW,
           const float* __restrict__ bb,  const float* __restrict__ hvec,
           const float* __restrict__ scale, const float* __restrict__ y0log,
           float* __restrict__ out)
{
    const int tid  = threadIdx.x;
    const int b    = blockIdx.x;
    const int warp = tid >> 5;
    const int lane = tid & 31;

    __shared__ __align__(16) float szf[WID];   // staged input vector
    __shared__ float sx[288];                  // g0: MLP input [h(256)|state(17)|pad]
    __shared__ float sbias[32];
    __shared__ float sbw[256];
    __shared__ float sk[NST];                  // g0: SEIR slopes (local)
    __shared__ float sbb_s[1];

    if (b < 32) {
        // ════════════════════ GROUP 0: layer0 + state owner ════════════════════
        const int lb = b;
        // W0 rows lb*32 + warp*4 + r, cols lane+32i (zero-padded)
        float w0r[4][9];
#pragma unroll
        for (int r = 0; r < 4; r++)
#pragma unroll
            for (int i = 0; i < 9; i++) {
                int col = lane + 32 * i;
                int row = lb * 32 + warp * 4 + r;
                w0r[r][i] = (warp < 8 && col < 273)
                            ? __ldg(&W0[row * 273 + col]) : 0.f;
            }
        if (tid < 32) sbias[tid] = b0[lb * 32 + tid];
        for (int i = tid; i < 256; i += TPB) sbw[i] = bW[i];
        if (tid == 0) sbb_s[0] = bb[0];
        if (tid >= NY && tid < 288) sx[tid] = 0.f;   // pad stays 0

        // per-thread state (tid<NY): y, k1..k3
        float y = 0.f, k1 = 0.f, k2 = 0.f, k3 = 0.f;
        if (tid < NY) {
            if (tid < NST) {
                float m = -1e30f;
                for (int i = 0; i < NST; i++) m = fmaxf(m, __ldg(&y0log[i]));
                float s = 0.f;
                for (int i = 0; i < NST; i++) s += expf(__ldg(&y0log[i]) - m);
                y = expf(__ldg(&y0log[tid]) - m) / s;
            } else {
                y = __ldg(&hvec[tid - NST]);
            }
        }
        __syncthreads();

        if (b == 0 && tid < NY) {                  // output row 0
            if (tid < NST) out[tid] = y;
            else           out[T_N * NST + (tid - NST)] = y;
        }

        unsigned n4 = 0;                           // dh publications consumed
        for (int iv = 0; iv < T_N - 1; ++iv) {
            float dt  = (__ldg(&ts[iv + 1]) - __ldg(&ts[iv])) * (1.f / (float)SUB);
            float dt6 = dt * (1.f / 6.f);
            for (int ss = 0; ss < SUB; ++ss) {
#pragma unroll
                for (int st = 0; st < 4; ++st) {
                    if (st > 0) { n4++; wait_lnk(4, 16u * n4); }
                    if (tid < NY) {
                        float xv = y;
                        if (st > 0) {
                            float kp = (tid < NST) ? sk[tid]
                                                   : __ldcg(&g_dh[tid - NST]);
                            if (st == 1) k1 = kp;
                            else if (st == 2) k2 = kp;
                            else k3 = kp;
                            xv = fmaf((st == 3) ? dt : 0.5f * dt, kp, y);
                        }
                        sx[(tid < NST) ? (HID + tid) : (tid - NST)] = xv;
                    }
                    __syncthreads();

                    if (warp < 8) {
                        // layer0: 4 rows per warp
                        float a0 = 0.f, a1 = 0.f, a2 = 0.f, a3 = 0.f;
#pragma unroll
                        for (int i = 0; i < 9; i++) {
                            float xv = sx[lane + 32 * i];
                            a0 = fmaf(w0r[0][i], xv, a0);
                            a1 = fmaf(w0r[1][i], xv, a1);
                            a2 = fmaf(w0r[2][i], xv, a2);
                            a3 = fmaf(w0r[3][i], xv, a3);
                        }
                        float v = reduce4(a0, a1, a2, a3, lane);
                        if (lane < 4)
                            __stcg(&g_zb[0][lb * 32 + warp * 4 + lane],
                                   softplus_f(v + sbias[warp * 4 + lane]));
                    } else {
                        // SEIR slopes: computed locally, stored to smem only
                        float t = 0.f;
#pragma unroll
                        for (int i = 0; i < 8; i++) {
                            int k = lane + 32 * i;
                            t = fmaf(sbw[k], sx[k], t);
                        }
                        t = warp_sum(t);
                        if (lane == 0) {
                            float bb1 = 8.f / (1.f + expf(-(t + sbb_s[0]))) + 25.f;
                            const float MU   = (float)(0.041 / 12.0);
                            const float XI   = (float)(13.0 / 12.0);
                            const float XIMU = (float)(13.0 / 12.0 + 0.041 / 12.0);
                            const float MUSG = (float)(0.041 / 12.0 + 91.0 / 12.0);
                            const float SG   = (float)(91.0 / 12.0);
                            const float NU   = (float)(36.0 / 12.0);
                            const float NUMU = (float)(36.0 / 12.0 + 0.041 / 12.0);
                            const float MUGA = (float)(0.041 / 12.0 + 1.8 / 12.0);
                            const float GA   = (float)(1.8 / 12.0);
                            const float* s_ = &sx[HID];
                            float M  = s_[0],  S1 = s_[1],  E1 = s_[2],  E2 = s_[3];
                            float E3 = s_[4],  E4 = s_[5],  I1 = s_[6],  I2 = s_[7];
                            float I3 = s_[8],  I4 = s_[9],  R1 = s_[10], R2 = s_[11];
                            float R3 = s_[12], R4 = s_[13], S2 = s_[14], S3 = s_[15];
                            float S4 = s_[16];
                            float I = I1 + I2 + I3 + I4;
                            float R = R1 + R2 + R3 + R4;
                            float bb2 = 0.5f * bb1, bb3 = 0.35f * bb1, bb4 = 0.25f * bb1;
                            sk[0]  = R * MU - XIMU * M;
                            sk[1]  = MU * (1.f - R) + XI * M - MU * S1 - bb1 * I * S1;
                            sk[2]  = bb1 * I * S1 - MUSG * E1;
                            sk[3]  = bb2 * I * S2 - MUSG * E2;
                            sk[4]  = bb3 * I * S3 - MUSG * E3;
                            sk[5]  = bb4 * I * S4 - MUSG * E4;
                            sk[6]  = SG * E1 - NUMU * I1;
                            sk[7]  = SG * E2 - NUMU * I2;
                            sk[8]  = SG * E3 - NUMU * I3;
                            sk[9]  = SG * E4 - NUMU * I4;
                            sk[10] = NU * I1 - MUGA * R1;
                            sk[11] = NU * I2 - MUGA * R2;
                            sk[12] = NU * I3 - MUGA * R3;
                            sk[13] = NU * I4 - MUGA * R4;
                            sk[14] = GA * R1 - MU * S2 - bb2 * I * S2;
                            sk[15] = GA * R2 - MU * S3 - bb3 * I * S3;
                            sk[16] = GA * (R3 + R4) - MU * S4 - bb4 * I * S4;
                        }
                    }
                    pub_lnk(0);
                } // st

                // RK4 combine: k4 = [sk (local), dh (link4)]
                n4++; wait_lnk(4, 16u * n4);
                if (tid < NY) {
                    float k4 = (tid < NST) ? sk[tid] : __ldcg(&g_dh[tid - NST]);
                    y = fmaf(dt6, k1 + 2.f * (k2 + k3) + k4, y);
                }
            } // ss

            if (b == 0 && tid < NY) {
                if (tid < NST) out[(iv + 1) * NST + tid] = y;
                else           out[T_N * NST + (iv + 1) * HID + (tid - NST)] = y;
            }
        } // iv

    } else if (b < 128) {
        // ════════════════════ GROUPS 1-3: hidden layers ════════════════════
        const int hl = (b >> 5) - 1;       // 0..2
        const int lb = b & 31;
        float4 wt[4][8];
#pragma unroll
        for (int r = 0; r < 4; r++)
#pragma unroll
            for (int i = 0; i < 8; i++)
                wt[r][i] = (warp < 8)
                    ? __ldg((const float4*)&Wh[((hl * WID) + (lb * 32 + warp * 4 + r))
                                               * WID + lane * 4 + 128 * i])
                    : make_float4(0.f, 0.f, 0.f, 0.f);
        if (tid < 32) sbias[tid] = bh[hl * WID + lb * 32 + tid];
        __syncthreads();

        unsigned n = 0;
        for (int it = 0; it < NSTAGE; ++it) {
            n++;
            wait_lnk(hl, 32u * n);                 // z[hl] ready
            if (tid < 256)
                ((float4*)szf)[tid] = __ldcg((const float4*)&g_zb[hl][tid * 4]);
            __syncthreads();
            if (warp < 8) {
                float a0 = 0.f, a1 = 0.f, a2 = 0.f, a3 = 0.f;
                const float4* z4 = (const float4*)szf;
#pragma unroll
                for (int i = 0; i < 8; i++) {
                    float4 z = z4[lane + 32 * i];
                    float4 q;
                    q = wt[0][i];
                    a0 = fmaf(q.x, z.x, a0); a0 = fmaf(q.y, z.y, a0);
                    a0 = fmaf(q.z, z.z, a0); a0 = fmaf(q.w, z.w, a0);
                    q = wt[1][i];
                    a1 = fmaf(q.x, z.x, a1); a1 = fmaf(q.y, z.y, a1);
                    a1 = fmaf(q.z, z.z, a1); a1 = fmaf(q.w, z.w, a1);
                    q = wt[2][i];
                    a2 = fmaf(q.x, z.x, a2); a2 = fmaf(q.y, z.y, a2);
                    a2 = fmaf(q.z, z.z, a2); a2 = fmaf(q.w, z.w, a2);
                    q = wt[3][i];
                    a3 = fmaf(q.x, z.x, a3); a3 = fmaf(q.y, z.y, a3);
                    a3 = fmaf(q.z, z.z, a3); a3 = fmaf(q.w, z.w, a3);
                }
                float v = reduce4(a0, a1, a2, a3, lane);
                if (lane < 4)
                    __stcg(&g_zb[hl + 1][lb * 32 + warp * 4 + lane],
                           softplus_f(v + sbias[warp * 4 + lane]));
            }
            pub_lnk(hl + 1);
        }

    } else {
        // ════════════════════ GROUP 4: final layer ════════════════════
        const int lb = b - 128;                    // 0..15, 16 rows each
        float4 wt[2][8];
#pragma unroll
        for (int r = 0; r < 2; r++)
#pragma unroll
            for (int i = 0; i < 8; i++)
                wt[r][i] = (warp < 8)
                    ? __ldg((const float4*)&Wl[(lb * 16 + warp * 2 + r) * WID
                                               + lane * 4 + 128 * i])
                    : make_float4(0.f, 0.f, 0.f, 0.f);
        if (tid < 16) sbias[tid] = bl[lb * 16 + tid];
        const float scl = scale[0];
        __syncthreads();

        unsigned n = 0;
        for (int it = 0; it < NSTAGE; ++it) {
            n++;
            wait_lnk(3, 32u * n);                  // z3 ready
            if (tid < 256)
                ((float4*)szf)[tid] = __ldcg((const float4*)&g_zb[3][tid * 4]);
            __syncthreads();
            if (warp < 8) {
                float a0 = 0.f, a1 = 0.f;
                const float4* z4 = (const float4*)szf;
#pragma unroll
                for (int i = 0; i < 8; i++) {
                    float4 z = z4[lane + 32 * i];
                    float4 q;
                    q = wt[0][i];
                    a0 = fmaf(q.x, z.x, a0); a0 = fmaf(q.y, z.y, a0);
                    a0 = fmaf(q.z, z.z, a0); a0 = fmaf(q.w, z.w, a0);
                    q = wt[1][i];
                    a1 = fmaf(q.x, z.x, a1); a1 = fmaf(q.y, z.y, a1);
                    a1 = fmaf(q.z, z.z, a1); a1 = fmaf(q.w, z.w, a1);
                }
                float v = reduce2(a0, a1, lane);
                if (lane < 2) {
                    float u = tanhf(0.01f * (v + sbias[warp * 2 + lane]));
                    __stcg(&g_dh[lb * 16 + warp * 2 + lane], scl * u);
                }
            }
            pub_lnk(4);
        }
    }
}

extern "C" void kernel_launch(void* const* d_in, const int* in_sizes, int n_in,
                              void* d_out, int out_size) {
    (void)in_sizes; (void)n_in; (void)out_size;
    const float* ts    = (const float*)d_in[0];
    const float* W0    = (const float*)d_in[1];
    const float* b0    = (const float*)d_in[2];
    const float* Wh    = (const float*)d_in[3];
    const float* bh    = (const float*)d_in[4];
    const float* Wl    = (const float*)d_in[5];
    const float* bl    = (const float*)d_in[6];
    const float* bW    = (const float*)d_in[7];
    const float* bb    = (const float*)d_in[8];
    const float* hvec  = (const float*)d_in[9];
    const float* scale = (const float*)d_in[10];
    const float* y0log = (const float*)d_in[11];
    float* out = (float*)d_out;

    reset_kernel<<<1, 1>>>();
    ode_kernel<<<NGRID, TPB>>>(ts, W0, b0, Wh, bh, Wl, bl, bW, bb,
                               hvec, scale, y0log, out);
}